// round 2
// baseline (speedup 1.0000x reference)
#include <cuda_runtime.h>
#include <math.h>

// Problem constants
// x: [16, 512, 32, 32]  -> B=16, C=512, N=H*W=1024
// qkv_weight: [1536, 512], proj_weight: [512, 512]

#define NBATCH 16
#define CCH    512
#define NPIX   1024

// Scratch (allocation-free rule: __device__ globals)
__device__ float g_xn  [NBATCH * CCH * NPIX];         // 32 MB groupnorm output
__device__ float g_qkv [NBATCH * 3 * CCH * NPIX];     // 96 MB
__device__ float g_attn[NBATCH * NPIX * NPIX];        // 64 MB
__device__ float g_o   [NBATCH * CCH * NPIX];         // 32 MB attention output

// ---------------------------------------------------------------------------
// GroupNorm: 32 groups, 16 channels x 1024 pixels per group
// grid = B*32 blocks, 256 threads
// ---------------------------------------------------------------------------
__global__ void gn_kernel(const float* __restrict__ x,
                          const float* __restrict__ w,
                          const float* __restrict__ bias,
                          float* __restrict__ xn) {
    int bg = blockIdx.x;
    int b = bg >> 5, g = bg & 31;
    const float* xp = x  + ((size_t)b * CCH + g * 16) * NPIX;
    float*       op = xn + ((size_t)b * CCH + g * 16) * NPIX;
    int tid = threadIdx.x;

    float s = 0.f, s2 = 0.f;
    for (int i = tid; i < 16 * NPIX; i += 256) {
        float v = xp[i];
        s += v; s2 += v * v;
    }
    __shared__ float red[256], red2[256];
    red[tid] = s; red2[tid] = s2;
    __syncthreads();
    for (int off = 128; off > 0; off >>= 1) {
        if (tid < off) { red[tid] += red[tid + off]; red2[tid] += red2[tid + off]; }
        __syncthreads();
    }
    float mean = red[0] * (1.f / 16384.f);
    float var  = red2[0] * (1.f / 16384.f) - mean * mean;
    float rstd = rsqrtf(var + 1e-5f);

    for (int i = tid; i < 16 * NPIX; i += 256) {
        int c = g * 16 + (i >> 10);
        op[i] = (xp[i] - mean) * rstd * w[c] + bias[c];
    }
}

// ---------------------------------------------------------------------------
// Generic tiled SGEMM: C[m,n] = sum_k A[.,.] * B[.,.]   (per blockIdx.z batch)
// BM = BN = 128, BK = 8, 256 threads, 8x8 per thread.
// AMODE: 0 -> A stored [k][m] (direct), 1 -> A stored [m][k] (transpose load)
// BMODE: 0 -> B stored [k][n] (direct), 1 -> B stored [n][k] (transpose load)
// EPI:   0 plain, 1 +biasM[m], 2 *scale, 3 +biasM[m]+Res[m][n]
// All dims assumed multiples of tile sizes (true here).
// ---------------------------------------------------------------------------
template<int AMODE, int BMODE, int EPI>
__global__ __launch_bounds__(256)
void gemm_kernel(const float* __restrict__ A, int lda, long long strideA,
                 const float* __restrict__ B, int ldb, long long strideB,
                 float* __restrict__ C, int ldc, long long strideC,
                 int K,
                 const float* __restrict__ biasM,
                 const float* __restrict__ Res, long long strideRes,
                 float scale) {
    __shared__ float As[8][128];
    __shared__ float Bs[8][128];

    int tid = threadIdx.x;
    int tx = tid & 15, ty = tid >> 4;
    int m0 = blockIdx.y * 128, n0 = blockIdx.x * 128;

    const float* Ab = A + (size_t)blockIdx.z * strideA;
    const float* Bb = B + (size_t)blockIdx.z * strideB;

    float acc[8][8] = {};

    for (int k0 = 0; k0 < K; k0 += 8) {
        // ---- load A tile into As[k][m] ----
        if (AMODE == 0) {
            int idx = tid * 4;
            int k = idx >> 7, m = idx & 127;
            float4 v = *(const float4*)(Ab + (size_t)(k0 + k) * lda + m0 + m);
            *(float4*)&As[k][m] = v;
        } else {
            int r = tid >> 1, c4 = (tid & 1) * 4;
            float4 v = *(const float4*)(Ab + (size_t)(m0 + r) * lda + k0 + c4);
            As[c4 + 0][r] = v.x; As[c4 + 1][r] = v.y;
            As[c4 + 2][r] = v.z; As[c4 + 3][r] = v.w;
        }
        // ---- load B tile into Bs[k][n] ----
        if (BMODE == 0) {
            int idx = tid * 4;
            int k = idx >> 7, n = idx & 127;
            float4 v = *(const float4*)(Bb + (size_t)(k0 + k) * ldb + n0 + n);
            *(float4*)&Bs[k][n] = v;
        } else {
            int r = tid >> 1, c4 = (tid & 1) * 4;
            float4 v = *(const float4*)(Bb + (size_t)(n0 + r) * ldb + k0 + c4);
            Bs[c4 + 0][r] = v.x; Bs[c4 + 1][r] = v.y;
            Bs[c4 + 2][r] = v.z; Bs[c4 + 3][r] = v.w;
        }
        __syncthreads();

        #pragma unroll
        for (int kk = 0; kk < 8; kk++) {
            float ra[8], rb[8];
            #pragma unroll
            for (int i = 0; i < 8; i++) ra[i] = As[kk][ty * 8 + i];
            #pragma unroll
            for (int j = 0; j < 8; j++) rb[j] = Bs[kk][tx * 8 + j];
            #pragma unroll
            for (int i = 0; i < 8; i++)
                #pragma unroll
                for (int j = 0; j < 8; j++)
                    acc[i][j] += ra[i] * rb[j];
        }
        __syncthreads();
    }

    float* Cb = C + (size_t)blockIdx.z * strideC;
    const float* Rb = (EPI == 3) ? (Res + (size_t)blockIdx.z * strideRes) : nullptr;

    #pragma unroll
    for (int i = 0; i < 8; i++) {
        int m = m0 + ty * 8 + i;
        float bm = (EPI == 1 || EPI == 3) ? biasM[m] : 0.f;
        #pragma unroll
        for (int j = 0; j < 8; j++) {
            int n = n0 + tx * 8 + j;
            float v = acc[i][j];
            if (EPI == 2) v *= scale;
            v += bm;
            if (EPI == 3) v += Rb[(size_t)m * ldc + n];
            Cb[(size_t)m * ldc + n] = v;
        }
    }
}

// ---------------------------------------------------------------------------
// Row softmax over 1024 elements. grid = B*NPIX blocks, 256 threads.
// ---------------------------------------------------------------------------
__global__ void softmax_kernel(float* __restrict__ attn) {
    float* p = attn + (size_t)blockIdx.x * NPIX;
    int tid = threadIdx.x;
    float v[4];
    float mx = -1e30f;
    #pragma unroll
    for (int i = 0; i < 4; i++) { v[i] = p[tid + i * 256]; mx = fmaxf(mx, v[i]); }

    __shared__ float red[256];
    red[tid] = mx;
    __syncthreads();
    for (int off = 128; off > 0; off >>= 1) {
        if (tid < off) red[tid] = fmaxf(red[tid], red[tid + off]);
        __syncthreads();
    }
    mx = red[0];
    __syncthreads();

    float s = 0.f;
    #pragma unroll
    for (int i = 0; i < 4; i++) { v[i] = __expf(v[i] - mx); s += v[i]; }
    red[tid] = s;
    __syncthreads();
    for (int off = 128; off > 0; off >>= 1) {
        if (tid < off) red[tid] += red[tid + off];
        __syncthreads();
    }
    float inv = 1.f / red[0];
    #pragma unroll
    for (int i = 0; i < 4; i++) p[tid + i * 256] = v[i] * inv;
}

// ---------------------------------------------------------------------------
extern "C" void kernel_launch(void* const* d_in, const int* in_sizes, int n_in,
                              void* d_out, int out_size) {
    const float* x     = (const float*)d_in[0];
    const float* gnw   = (const float*)d_in[1];
    const float* gnb   = (const float*)d_in[2];
    const float* qkvw  = (const float*)d_in[3];
    const float* qkvb  = (const float*)d_in[4];
    const float* projw = (const float*)d_in[5];
    const float* projb = (const float*)d_in[6];
    float* out = (float*)d_out;

    float *xn, *qkv, *attn, *obuf;
    cudaGetSymbolAddress((void**)&xn,   g_xn);
    cudaGetSymbolAddress((void**)&qkv,  g_qkv);
    cudaGetSymbolAddress((void**)&attn, g_attn);
    cudaGetSymbolAddress((void**)&obuf, g_o);

    const long long sXN   = (long long)CCH * NPIX;          // 512*1024
    const long long sQKV  = (long long)3 * CCH * NPIX;      // 1536*1024
    const long long sATT  = (long long)NPIX * NPIX;         // 1024*1024
    const float inv_sqrt_c = 0.044194173824159216f;         // 512^-0.5

    // 1. GroupNorm
    gn_kernel<<<NBATCH * 32, 256>>>(x, gnw, gnb, xn);

    // 2. QKV GEMM: C[o,n] = sum_c W[o,c] * xn[c,n] + qkv_bias[o]
    //    A = W [m][k] (trans), B = xn [k][n] (direct)
    gemm_kernel<1, 0, 1><<<dim3(NPIX / 128, 1536 / 128, NBATCH), 256>>>(
        qkvw, CCH, 0,
        xn, NPIX, sXN,
        qkv, NPIX, sQKV,
        CCH, qkvb, nullptr, 0, 1.f);

    // 3. S = Q^T K * C^-0.5 : C[n,m'] = sum_c q[c,n]*k[c,m']
    //    A = q [k][m] direct, B = k [k][n] direct
    gemm_kernel<0, 0, 2><<<dim3(NPIX / 128, NPIX / 128, NBATCH), 256>>>(
        qkv, NPIX, sQKV,
        qkv + (size_t)CCH * NPIX, NPIX, sQKV,
        attn, NPIX, sATT,
        CCH, nullptr, nullptr, 0, inv_sqrt_c);

    // 4. softmax rows
    softmax_kernel<<<NBATCH * NPIX, 256>>>(attn);

    // 5. O = V P^T : C[c,n] = sum_m V[c,m] * P[n,m]
    //    A = V [m][k] trans, B = P [n][k] trans
    gemm_kernel<1, 1, 0><<<dim3(NPIX / 128, CCH / 128, NBATCH), 256>>>(
        qkv + (size_t)2 * CCH * NPIX, NPIX, sQKV,
        attn, NPIX, sATT,
        obuf, NPIX, sXN,
        NPIX, nullptr, nullptr, 0, 1.f);

    // 6. out = proj(O) + proj_bias + O
    gemm_kernel<1, 0, 3><<<dim3(NPIX / 128, CCH / 128, NBATCH), 256>>>(
        projw, CCH, 0,
        obuf, NPIX, sXN,
        out, NPIX, sXN,
        CCH, projb, obuf, sXN, 1.f);
}

// round 3
// speedup vs baseline: 2.9081x; 2.9081x over previous
#include <cuda_runtime.h>
#include <math.h>
#include <stdint.h>

// Problem: x [16,512,32,32] -> B=16, C=512, N=1024
#define NBATCH 16
#define CCH    512
#define NPIX   1024

// Scratch (allocation-free rule: __device__ globals)
__device__ float g_xn  [NBATCH * CCH * NPIX];
__device__ float g_qkv [NBATCH * 3 * CCH * NPIX];
__device__ float g_attn[NBATCH * NPIX * NPIX];
__device__ float g_o   [NBATCH * CCH * NPIX];

// ---------------------------------------------------------------------------
// GroupNorm
// ---------------------------------------------------------------------------
__global__ void gn_kernel(const float* __restrict__ x,
                          const float* __restrict__ w,
                          const float* __restrict__ bias,
                          float* __restrict__ xn) {
    int bg = blockIdx.x;
    int b = bg >> 5, g = bg & 31;
    const float* xp = x  + ((size_t)b * CCH + g * 16) * NPIX;
    float*       op = xn + ((size_t)b * CCH + g * 16) * NPIX;
    int tid = threadIdx.x;

    float s = 0.f, s2 = 0.f;
    for (int i = tid; i < 16 * NPIX; i += 256) {
        float v = xp[i];
        s += v; s2 += v * v;
    }
    __shared__ float red[256], red2[256];
    red[tid] = s; red2[tid] = s2;
    __syncthreads();
    for (int off = 128; off > 0; off >>= 1) {
        if (tid < off) { red[tid] += red[tid + off]; red2[tid] += red2[tid + off]; }
        __syncthreads();
    }
    float mean = red[0] * (1.f / 16384.f);
    float var  = red2[0] * (1.f / 16384.f) - mean * mean;
    float rstd = rsqrtf(var + 1e-5f);

    for (int i = tid; i < 16 * NPIX; i += 256) {
        int c = g * 16 + (i >> 10);
        op[i] = (xp[i] - mean) * rstd * w[c] + bias[c];
    }
}

// ---------------------------------------------------------------------------
// tf32 helpers
// ---------------------------------------------------------------------------
__device__ __forceinline__ uint32_t f2tf32(float x) {
    uint32_t r;
    asm("cvt.rna.tf32.f32 %0, %1;" : "=r"(r) : "f"(x));
    return r;
}

__device__ __forceinline__ void mma_tf32(float& c0, float& c1, float& c2, float& c3,
                                         uint32_t a0, uint32_t a1, uint32_t a2, uint32_t a3,
                                         uint32_t b0, uint32_t b1) {
    asm volatile(
        "mma.sync.aligned.m16n8k8.row.col.f32.tf32.tf32.f32 "
        "{%0,%1,%2,%3}, {%4,%5,%6,%7}, {%8,%9}, {%0,%1,%2,%3};\n"
        : "+f"(c0), "+f"(c1), "+f"(c2), "+f"(c3)
        : "r"(a0), "r"(a1), "r"(a2), "r"(a3), "r"(b0), "r"(b1));
}

// ---------------------------------------------------------------------------
// Tile fetch/store. Tile is 128 (m/n) x 16 (k). SMEM layout [k][m] stride 136
// (136 % 32 == 8 -> fragment loads bank-conflict-free).
// MODE 0: gmem [k][m] (direct).  MODE 1: gmem [m][k] (transpose on store).
// ---------------------------------------------------------------------------
#define SMSTR 136

template<int MODE>
__device__ __forceinline__ void fetch_tile(const float* __restrict__ P, int ld,
                                           int k0, int off0, int tid, float4 v[2]) {
    if (MODE == 0) {
        int k = tid >> 5, c = (tid & 31) * 4;
        #pragma unroll
        for (int i = 0; i < 2; i++)
            v[i] = *(const float4*)(P + (size_t)(k0 + k + 8 * i) * ld + off0 + c);
    } else {
        int r = tid >> 2, k = (tid & 3) * 4;
        #pragma unroll
        for (int i = 0; i < 2; i++)
            v[i] = *(const float4*)(P + (size_t)(off0 + r + 64 * i) * ld + k0 + k);
    }
}

template<int MODE>
__device__ __forceinline__ void store_tile(uint32_t* __restrict__ S, int tid,
                                           const float4 v[2]) {
    if (MODE == 0) {
        int k = tid >> 5, c = (tid & 31) * 4;
        #pragma unroll
        for (int i = 0; i < 2; i++) {
            uint32_t* p = S + (k + 8 * i) * SMSTR + c;
            p[0] = f2tf32(v[i].x); p[1] = f2tf32(v[i].y);
            p[2] = f2tf32(v[i].z); p[3] = f2tf32(v[i].w);
        }
    } else {
        int r = tid >> 2, k = (tid & 3) * 4;
        #pragma unroll
        for (int i = 0; i < 2; i++) {
            int rr = r + 64 * i;
            S[(k + 0) * SMSTR + rr] = f2tf32(v[i].x);
            S[(k + 1) * SMSTR + rr] = f2tf32(v[i].y);
            S[(k + 2) * SMSTR + rr] = f2tf32(v[i].z);
            S[(k + 3) * SMSTR + rr] = f2tf32(v[i].w);
        }
    }
}

// ---------------------------------------------------------------------------
// Tensor-core GEMM: C[m,n] = sum_k opA * opB per batch z.
// BM=BN=128, BK=16, 256 threads, 8 warps (2x4), warp tile 64x32,
// mma.m16n8k8.tf32, fragments 4x4 per warp, fp32 accumulate.
// EPI: 0 plain, 1 +biasM[m], 2 *scale, 3 +biasM[m]+Res[m][n]
// ---------------------------------------------------------------------------
template<int AMODE, int BMODE, int EPI>
__global__ __launch_bounds__(256)
void gemm_tc(const float* __restrict__ A, int lda, long long strideA,
             const float* __restrict__ B, int ldb, long long strideB,
             float* __restrict__ C, int ldc, long long strideC,
             int K,
             const float* __restrict__ biasM,
             const float* __restrict__ Res, long long strideRes,
             float scale) {
    __shared__ uint32_t As[2][16 * SMSTR];
    __shared__ uint32_t Bs[2][16 * SMSTR];

    const int tid = threadIdx.x, lane = tid & 31, w = tid >> 5;
    const int wm = w >> 2, wn = w & 3;          // 2 x 4 warp grid
    const int g = lane >> 2, t = lane & 3;      // mma fragment coords
    const int m0 = blockIdx.y * 128, n0 = blockIdx.x * 128;

    const float* Ab = A + (size_t)blockIdx.z * strideA;
    const float* Bb = B + (size_t)blockIdx.z * strideB;

    float acc[4][4][4];
    #pragma unroll
    for (int i = 0; i < 4; i++)
        #pragma unroll
        for (int j = 0; j < 4; j++)
            #pragma unroll
            for (int c = 0; c < 4; c++) acc[i][j][c] = 0.f;

    float4 ra[2], rb[2];
    fetch_tile<AMODE>(Ab, lda, 0, m0, tid, ra);
    fetch_tile<BMODE>(Bb, ldb, 0, n0, tid, rb);
    store_tile<AMODE>(As[0], tid, ra);
    store_tile<BMODE>(Bs[0], tid, rb);
    __syncthreads();

    int cur = 0;
    for (int k0 = 0; k0 < K; k0 += 16) {
        bool has_next = (k0 + 16 < K);
        if (has_next) {
            fetch_tile<AMODE>(Ab, lda, k0 + 16, m0, tid, ra);
            fetch_tile<BMODE>(Bb, ldb, k0 + 16, n0, tid, rb);
        }

        #pragma unroll
        for (int kk = 0; kk < 16; kk += 8) {
            uint32_t af[4][4];
            uint32_t bf[4][2];
            const uint32_t* Ac = As[cur] + (kk + t) * SMSTR;
            const uint32_t* Ac4 = As[cur] + (kk + t + 4) * SMSTR;
            const uint32_t* Bc = Bs[cur] + (kk + t) * SMSTR;
            const uint32_t* Bc4 = Bs[cur] + (kk + t + 4) * SMSTR;
            #pragma unroll
            for (int mf = 0; mf < 4; mf++) {
                int mrow = wm * 64 + mf * 16 + g;
                af[mf][0] = Ac[mrow];
                af[mf][1] = Ac[mrow + 8];
                af[mf][2] = Ac4[mrow];
                af[mf][3] = Ac4[mrow + 8];
            }
            #pragma unroll
            for (int nf = 0; nf < 4; nf++) {
                int ncol = wn * 32 + nf * 8 + g;
                bf[nf][0] = Bc[ncol];
                bf[nf][1] = Bc4[ncol];
            }
            #pragma unroll
            for (int mf = 0; mf < 4; mf++)
                #pragma unroll
                for (int nf = 0; nf < 4; nf++)
                    mma_tf32(acc[mf][nf][0], acc[mf][nf][1],
                             acc[mf][nf][2], acc[mf][nf][3],
                             af[mf][0], af[mf][1], af[mf][2], af[mf][3],
                             bf[nf][0], bf[nf][1]);
        }

        if (has_next) {
            int nxt = cur ^ 1;
            store_tile<AMODE>(As[nxt], tid, ra);
            store_tile<BMODE>(Bs[nxt], tid, rb);
            __syncthreads();
            cur = nxt;
        }
    }

    float* Cb = C + (size_t)blockIdx.z * strideC;
    const float* Rb = (EPI == 3) ? (Res + (size_t)blockIdx.z * strideRes) : nullptr;

    #pragma unroll
    for (int mf = 0; mf < 4; mf++) {
        int m = m0 + wm * 64 + mf * 16 + g;
        float bm0 = 0.f, bm1 = 0.f;
        if (EPI == 1 || EPI == 3) { bm0 = biasM[m]; bm1 = biasM[m + 8]; }
        #pragma unroll
        for (int nf = 0; nf < 4; nf++) {
            int n = n0 + wn * 32 + nf * 8 + t * 2;
            float v0 = acc[mf][nf][0], v1 = acc[mf][nf][1];
            float v2 = acc[mf][nf][2], v3 = acc[mf][nf][3];
            if (EPI == 2) { v0 *= scale; v1 *= scale; v2 *= scale; v3 *= scale; }
            v0 += bm0; v1 += bm0; v2 += bm1; v3 += bm1;
            if (EPI == 3) {
                const float* r0 = Rb + (size_t)m * ldc + n;
                const float* r1 = Rb + (size_t)(m + 8) * ldc + n;
                v0 += r0[0]; v1 += r0[1];
                v2 += r1[0]; v3 += r1[1];
            }
            *(float2*)(Cb + (size_t)m * ldc + n)       = make_float2(v0, v1);
            *(float2*)(Cb + (size_t)(m + 8) * ldc + n) = make_float2(v2, v3);
        }
    }
}

// ---------------------------------------------------------------------------
// Row softmax over 1024 elements
// ---------------------------------------------------------------------------
__global__ void softmax_kernel(float* __restrict__ attn) {
    float* p = attn + (size_t)blockIdx.x * NPIX;
    int tid = threadIdx.x;
    float v[4];
    float mx = -1e30f;
    #pragma unroll
    for (int i = 0; i < 4; i++) { v[i] = p[tid + i * 256]; mx = fmaxf(mx, v[i]); }

    __shared__ float red[256];
    red[tid] = mx;
    __syncthreads();
    for (int off = 128; off > 0; off >>= 1) {
        if (tid < off) red[tid] = fmaxf(red[tid], red[tid + off]);
        __syncthreads();
    }
    mx = red[0];
    __syncthreads();

    float s = 0.f;
    #pragma unroll
    for (int i = 0; i < 4; i++) { v[i] = __expf(v[i] - mx); s += v[i]; }
    red[tid] = s;
    __syncthreads();
    for (int off = 128; off > 0; off >>= 1) {
        if (tid < off) red[tid] += red[tid + off];
        __syncthreads();
    }
    float inv = 1.f / red[0];
    #pragma unroll
    for (int i = 0; i < 4; i++) p[tid + i * 256] = v[i] * inv;
}

// ---------------------------------------------------------------------------
extern "C" void kernel_launch(void* const* d_in, const int* in_sizes, int n_in,
                              void* d_out, int out_size) {
    const float* x     = (const float*)d_in[0];
    const float* gnw   = (const float*)d_in[1];
    const float* gnb   = (const float*)d_in[2];
    const float* qkvw  = (const float*)d_in[3];
    const float* qkvb  = (const float*)d_in[4];
    const float* projw = (const float*)d_in[5];
    const float* projb = (const float*)d_in[6];
    float* out = (float*)d_out;

    float *xn, *qkv, *attn, *obuf;
    cudaGetSymbolAddress((void**)&xn,   g_xn);
    cudaGetSymbolAddress((void**)&qkv,  g_qkv);
    cudaGetSymbolAddress((void**)&attn, g_attn);
    cudaGetSymbolAddress((void**)&obuf, g_o);

    const long long sXN  = (long long)CCH * NPIX;
    const long long sQKV = (long long)3 * CCH * NPIX;
    const long long sATT = (long long)NPIX * NPIX;
    const float inv_sqrt_c = 0.044194173824159216f;  // 512^-0.5

    // 1. GroupNorm
    gn_kernel<<<NBATCH * 32, 256>>>(x, gnw, gnb, xn);

    // 2. QKV GEMM: C[o,n] = sum_c W[o,c] * xn[c,n] + bias[o]
    gemm_tc<1, 0, 1><<<dim3(NPIX / 128, 1536 / 128, NBATCH), 256>>>(
        qkvw, CCH, 0,
        xn, NPIX, sXN,
        qkv, NPIX, sQKV,
        CCH, qkvb, nullptr, 0, 1.f);

    // 3. S[n,m'] = sum_c q[c,n] k[c,m'] * C^-0.5
    gemm_tc<0, 0, 2><<<dim3(NPIX / 128, NPIX / 128, NBATCH), 256>>>(
        qkv, NPIX, sQKV,
        qkv + (size_t)CCH * NPIX, NPIX, sQKV,
        attn, NPIX, sATT,
        CCH, nullptr, nullptr, 0, inv_sqrt_c);

    // 4. softmax rows
    softmax_kernel<<<NBATCH * NPIX, 256>>>(attn);

    // 5. O[c,n] = sum_m V[c,m] P[n,m]
    gemm_tc<1, 1, 0><<<dim3(NPIX / 128, CCH / 128, NBATCH), 256>>>(
        qkv + (size_t)2 * CCH * NPIX, NPIX, sQKV,
        attn, NPIX, sATT,
        obuf, NPIX, sXN,
        NPIX, nullptr, nullptr, 0, 1.f);

    // 6. out = proj(O) + proj_bias + O
    gemm_tc<1, 0, 3><<<dim3(NPIX / 128, CCH / 128, NBATCH), 256>>>(
        projw, CCH, 0,
        obuf, NPIX, sXN,
        out, NPIX, sXN,
        CCH, projb, obuf, sXN, 1.f);
}

// round 4
// speedup vs baseline: 4.0568x; 1.3950x over previous
#include <cuda_runtime.h>
#include <cuda_fp16.h>
#include <math.h>
#include <stdint.h>

// Problem: x [16,512,32,32] -> B=16, C=512, N=1024
#define NBATCH 16
#define CCH    512
#define NPIX   1024

// Scratch (allocation-free rule: __device__ globals)
__device__ float g_xn  [NBATCH * CCH * NPIX];
__device__ float g_qkv [NBATCH * 3 * CCH * NPIX];
__device__ float g_attn[NBATCH * NPIX * NPIX];
__device__ float g_o   [NBATCH * CCH * NPIX];

// ---------------------------------------------------------------------------
// GroupNorm
// ---------------------------------------------------------------------------
__global__ void gn_kernel(const float* __restrict__ x,
                          const float* __restrict__ w,
                          const float* __restrict__ bias,
                          float* __restrict__ xn) {
    int bg = blockIdx.x;
    int b = bg >> 5, g = bg & 31;
    const float* xp = x  + ((size_t)b * CCH + g * 16) * NPIX;
    float*       op = xn + ((size_t)b * CCH + g * 16) * NPIX;
    int tid = threadIdx.x;

    float s = 0.f, s2 = 0.f;
    for (int i = tid; i < 16 * NPIX; i += 256) {
        float v = xp[i];
        s += v; s2 += v * v;
    }
    __shared__ float red[256], red2[256];
    red[tid] = s; red2[tid] = s2;
    __syncthreads();
    for (int off = 128; off > 0; off >>= 1) {
        if (tid < off) { red[tid] += red[tid + off]; red2[tid] += red2[tid + off]; }
        __syncthreads();
    }
    float mean = red[0] * (1.f / 16384.f);
    float var  = red2[0] * (1.f / 16384.f) - mean * mean;
    float rstd = rsqrtf(var + 1e-5f);

    for (int i = tid; i < 16 * NPIX; i += 256) {
        int c = g * 16 + (i >> 10);
        op[i] = (xp[i] - mean) * rstd * w[c] + bias[c];
    }
}

// ---------------------------------------------------------------------------
// fp16 helpers
// ---------------------------------------------------------------------------
__device__ __forceinline__ uint32_t pack2(float x, float y) {
    __half2 h = __floats2half2_rn(x, y);
    return *reinterpret_cast<uint32_t*>(&h);
}

__device__ __forceinline__ void mma_f16(float& c0, float& c1, float& c2, float& c3,
                                        uint32_t a0, uint32_t a1, uint32_t a2, uint32_t a3,
                                        uint32_t b0, uint32_t b1) {
    asm volatile(
        "mma.sync.aligned.m16n8k16.row.col.f32.f16.f16.f32 "
        "{%0,%1,%2,%3}, {%4,%5,%6,%7}, {%8,%9}, {%0,%1,%2,%3};\n"
        : "+f"(c0), "+f"(c1), "+f"(c2), "+f"(c3)
        : "r"(a0), "r"(a1), "r"(a2), "r"(a3), "r"(b0), "r"(b1));
}

// ---------------------------------------------------------------------------
// Tile fetch/store. Tile covers 128 (m/n) x 16 (k) fp32 values, stored in SMEM
// as uint32 = fp16x2 packed along k: S[kp][m], kp in [0,8), stride 136
// (136 % 32 == 8 -> fragment loads bank-conflict-free).
// MODE 0: gmem [k][m] (direct).  MODE 1: gmem [m][k] (transpose on store).
// ---------------------------------------------------------------------------
#define SMSTR 136

template<int MODE>
__device__ __forceinline__ void fetch_tile(const float* __restrict__ P, int ld,
                                           int k0, int off0, int tid, float4 v[2]) {
    if (MODE == 0) {
        // thread owns k-pair kp = tid>>5 (rows 2kp, 2kp+1), 4 m's
        int kp = tid >> 5, m4 = (tid & 31) * 4;
        v[0] = *(const float4*)(P + (size_t)(k0 + 2 * kp)     * ld + off0 + m4);
        v[1] = *(const float4*)(P + (size_t)(k0 + 2 * kp + 1) * ld + off0 + m4);
    } else {
        // thread owns row r (and r+64), 4 consecutive k
        int r = tid >> 2, k4 = (tid & 3) * 4;
        v[0] = *(const float4*)(P + (size_t)(off0 + r)      * ld + k0 + k4);
        v[1] = *(const float4*)(P + (size_t)(off0 + r + 64) * ld + k0 + k4);
    }
}

template<int MODE>
__device__ __forceinline__ void store_tile(uint32_t* __restrict__ S, int tid,
                                           const float4 v[2]) {
    if (MODE == 0) {
        int kp = tid >> 5, m4 = (tid & 31) * 4;
        uint32_t* p = S + kp * SMSTR + m4;
        p[0] = pack2(v[0].x, v[1].x);
        p[1] = pack2(v[0].y, v[1].y);
        p[2] = pack2(v[0].z, v[1].z);
        p[3] = pack2(v[0].w, v[1].w);
    } else {
        int r = tid >> 2, kp = (tid & 3) * 2;
        S[kp * SMSTR + r]            = pack2(v[0].x, v[0].y);
        S[(kp + 1) * SMSTR + r]      = pack2(v[0].z, v[0].w);
        S[kp * SMSTR + r + 64]       = pack2(v[1].x, v[1].y);
        S[(kp + 1) * SMSTR + r + 64] = pack2(v[1].z, v[1].w);
    }
}

// ---------------------------------------------------------------------------
// Tensor-core GEMM (fp16 inputs, fp32 accum): C[m,n] = sum_k opA * opB.
// BM=BN=128, BK=16, 256 threads, 8 warps (2x4), warp tile 64x32,
// mma.m16n8k16.f16, fragments 4x4 per warp.
// EPI: 0 plain, 1 +biasM[m], 2 *scale, 3 +biasM[m]+Res[m][n]
// ---------------------------------------------------------------------------
template<int AMODE, int BMODE, int EPI>
__global__ __launch_bounds__(256)
void gemm_tc(const float* __restrict__ A, int lda, long long strideA,
             const float* __restrict__ B, int ldb, long long strideB,
             float* __restrict__ C, int ldc, long long strideC,
             int K,
             const float* __restrict__ biasM,
             const float* __restrict__ Res, long long strideRes,
             float scale) {
    __shared__ uint32_t As[2][8 * SMSTR];
    __shared__ uint32_t Bs[2][8 * SMSTR];

    const int tid = threadIdx.x, lane = tid & 31, w = tid >> 5;
    const int wm = w >> 2, wn = w & 3;          // 2 x 4 warp grid
    const int g = lane >> 2, t = lane & 3;      // mma fragment coords
    const int m0 = blockIdx.y * 128, n0 = blockIdx.x * 128;

    const float* Ab = A + (size_t)blockIdx.z * strideA;
    const float* Bb = B + (size_t)blockIdx.z * strideB;

    float acc[4][4][4];
    #pragma unroll
    for (int i = 0; i < 4; i++)
        #pragma unroll
        for (int j = 0; j < 4; j++)
            #pragma unroll
            for (int c = 0; c < 4; c++) acc[i][j][c] = 0.f;

    float4 ra[2], rb[2];
    fetch_tile<AMODE>(Ab, lda, 0, m0, tid, ra);
    fetch_tile<BMODE>(Bb, ldb, 0, n0, tid, rb);
    store_tile<AMODE>(As[0], tid, ra);
    store_tile<BMODE>(Bs[0], tid, rb);
    __syncthreads();

    int cur = 0;
    for (int k0 = 0; k0 < K; k0 += 16) {
        bool has_next = (k0 + 16 < K);
        if (has_next) {
            fetch_tile<AMODE>(Ab, lda, k0 + 16, m0, tid, ra);
            fetch_tile<BMODE>(Bb, ldb, k0 + 16, n0, tid, rb);
        }

        // one m16n8k16 pass consumes all 8 k-pairs of this tile
        {
            uint32_t af[4][4];
            uint32_t bf[4][2];
            const uint32_t* Ac  = As[cur] + t * SMSTR;
            const uint32_t* Ac4 = As[cur] + (t + 4) * SMSTR;
            const uint32_t* Bc  = Bs[cur] + t * SMSTR;
            const uint32_t* Bc4 = Bs[cur] + (t + 4) * SMSTR;
            #pragma unroll
            for (int mf = 0; mf < 4; mf++) {
                int mrow = wm * 64 + mf * 16 + g;
                af[mf][0] = Ac[mrow];        // rows g,   k-pair t
                af[mf][1] = Ac[mrow + 8];    // rows g+8, k-pair t
                af[mf][2] = Ac4[mrow];       // rows g,   k-pair t+4
                af[mf][3] = Ac4[mrow + 8];   // rows g+8, k-pair t+4
            }
            #pragma unroll
            for (int nf = 0; nf < 4; nf++) {
                int ncol = wn * 32 + nf * 8 + g;
                bf[nf][0] = Bc[ncol];        // k-pair t
                bf[nf][1] = Bc4[ncol];       // k-pair t+4
            }
            #pragma unroll
            for (int mf = 0; mf < 4; mf++)
                #pragma unroll
                for (int nf = 0; nf < 4; nf++)
                    mma_f16(acc[mf][nf][0], acc[mf][nf][1],
                            acc[mf][nf][2], acc[mf][nf][3],
                            af[mf][0], af[mf][1], af[mf][2], af[mf][3],
                            bf[nf][0], bf[nf][1]);
        }

        if (has_next) {
            int nxt = cur ^ 1;
            store_tile<AMODE>(As[nxt], tid, ra);
            store_tile<BMODE>(Bs[nxt], tid, rb);
            __syncthreads();
            cur = nxt;
        }
    }

    float* Cb = C + (size_t)blockIdx.z * strideC;
    const float* Rb = (EPI == 3) ? (Res + (size_t)blockIdx.z * strideRes) : nullptr;

    #pragma unroll
    for (int mf = 0; mf < 4; mf++) {
        int m = m0 + wm * 64 + mf * 16 + g;
        float bm0 = 0.f, bm1 = 0.f;
        if (EPI == 1 || EPI == 3) { bm0 = biasM[m]; bm1 = biasM[m + 8]; }
        #pragma unroll
        for (int nf = 0; nf < 4; nf++) {
            int n = n0 + wn * 32 + nf * 8 + t * 2;
            float v0 = acc[mf][nf][0], v1 = acc[mf][nf][1];
            float v2 = acc[mf][nf][2], v3 = acc[mf][nf][3];
            if (EPI == 2) { v0 *= scale; v1 *= scale; v2 *= scale; v3 *= scale; }
            v0 += bm0; v1 += bm0; v2 += bm1; v3 += bm1;
            if (EPI == 3) {
                const float* r0 = Rb + (size_t)m * ldc + n;
                const float* r1 = Rb + (size_t)(m + 8) * ldc + n;
                v0 += r0[0]; v1 += r0[1];
                v2 += r1[0]; v3 += r1[1];
            }
            *(float2*)(Cb + (size_t)m * ldc + n)       = make_float2(v0, v1);
            *(float2*)(Cb + (size_t)(m + 8) * ldc + n) = make_float2(v2, v3);
        }
    }
}

// ---------------------------------------------------------------------------
// Row softmax over 1024 elements
// ---------------------------------------------------------------------------
__global__ void softmax_kernel(float* __restrict__ attn) {
    float* p = attn + (size_t)blockIdx.x * NPIX;
    int tid = threadIdx.x;
    float v[4];
    float mx = -1e30f;
    #pragma unroll
    for (int i = 0; i < 4; i++) { v[i] = p[tid + i * 256]; mx = fmaxf(mx, v[i]); }

    __shared__ float red[256];
    red[tid] = mx;
    __syncthreads();
    for (int off = 128; off > 0; off >>= 1) {
        if (tid < off) red[tid] = fmaxf(red[tid], red[tid + off]);
        __syncthreads();
    }
    mx = red[0];
    __syncthreads();

    float s = 0.f;
    #pragma unroll
    for (int i = 0; i < 4; i++) { v[i] = __expf(v[i] - mx); s += v[i]; }
    red[tid] = s;
    __syncthreads();
    for (int off = 128; off > 0; off >>= 1) {
        if (tid < off) red[tid] += red[tid + off];
        __syncthreads();
    }
    float inv = 1.f / red[0];
    #pragma unroll
    for (int i = 0; i < 4; i++) p[tid + i * 256] = v[i] * inv;
}

// ---------------------------------------------------------------------------
extern "C" void kernel_launch(void* const* d_in, const int* in_sizes, int n_in,
                              void* d_out, int out_size) {
    const float* x     = (const float*)d_in[0];
    const float* gnw   = (const float*)d_in[1];
    const float* gnb   = (const float*)d_in[2];
    const float* qkvw  = (const float*)d_in[3];
    const float* qkvb  = (const float*)d_in[4];
    const float* projw = (const float*)d_in[5];
    const float* projb = (const float*)d_in[6];
    float* out = (float*)d_out;

    float *xn, *qkv, *attn, *obuf;
    cudaGetSymbolAddress((void**)&xn,   g_xn);
    cudaGetSymbolAddress((void**)&qkv,  g_qkv);
    cudaGetSymbolAddress((void**)&attn, g_attn);
    cudaGetSymbolAddress((void**)&obuf, g_o);

    const long long sXN  = (long long)CCH * NPIX;
    const long long sQKV = (long long)3 * CCH * NPIX;
    const long long sATT = (long long)NPIX * NPIX;
    const float inv_sqrt_c = 0.044194173824159216f;  // 512^-0.5

    // 1. GroupNorm
    gn_kernel<<<NBATCH * 32, 256>>>(x, gnw, gnb, xn);

    // 2. QKV GEMM: C[o,n] = sum_c W[o,c] * xn[c,n] + bias[o]
    gemm_tc<1, 0, 1><<<dim3(NPIX / 128, 1536 / 128, NBATCH), 256>>>(
        qkvw, CCH, 0,
        xn, NPIX, sXN,
        qkv, NPIX, sQKV,
        CCH, qkvb, nullptr, 0, 1.f);

    // 3. S[n,m'] = sum_c q[c,n] k[c,m'] * C^-0.5
    gemm_tc<0, 0, 2><<<dim3(NPIX / 128, NPIX / 128, NBATCH), 256>>>(
        qkv, NPIX, sQKV,
        qkv + (size_t)CCH * NPIX, NPIX, sQKV,
        attn, NPIX, sATT,
        CCH, nullptr, nullptr, 0, inv_sqrt_c);

    // 4. softmax rows
    softmax_kernel<<<NBATCH * NPIX, 256>>>(attn);

    // 5. O[c,n] = sum_m V[c,m] P[n,m]
    gemm_tc<1, 1, 0><<<dim3(NPIX / 128, CCH / 128, NBATCH), 256>>>(
        qkv + (size_t)2 * CCH * NPIX, NPIX, sQKV,
        attn, NPIX, sATT,
        obuf, NPIX, sXN,
        NPIX, nullptr, nullptr, 0, 1.f);

    // 6. out = proj(O) + proj_bias + O
    gemm_tc<1, 0, 3><<<dim3(NPIX / 128, CCH / 128, NBATCH), 256>>>(
        projw, CCH, 0,
        obuf, NPIX, sXN,
        out, NPIX, sXN,
        CCH, projb, obuf, sXN, 1.f);
}

// round 6
// speedup vs baseline: 4.6883x; 1.1557x over previous
#include <cuda_runtime.h>
#include <cuda_fp16.h>
#include <math.h>
#include <stdint.h>

// Problem: x [16,512,32,32] -> B=16, C=512, N=1024
#define NBATCH 16
#define CCH    512
#define NPIX   1024

// ---------------------------------------------------------------------------
// Scratch (__device__ globals; no allocation allowed)
// ---------------------------------------------------------------------------
__device__ __half g_xn  [NBATCH * CCH * NPIX];        // fp16 [b][c][n]
__device__ __half g_wqkv[3 * CCH * CCH];              // fp16 qkv weight
__device__ __half g_wprj[CCH * CCH];                  // fp16 proj weight
__device__ __half g_qkv [NBATCH * 3 * CCH * NPIX];    // fp16 [b][o][n]
__device__ float  g_S   [NBATCH * NPIX * NPIX];       // fp32 scores
__device__ __half g_P   [NBATCH * NPIX * NPIX];       // fp16 probs
__device__ __half g_Oh  [NBATCH * CCH * NPIX];        // fp16 attn out
__device__ float  g_Of  [NBATCH * CCH * NPIX];        // fp32 attn out (residual)

// ---------------------------------------------------------------------------
// GroupNorm -> fp16 xn [b][c][n]
// ---------------------------------------------------------------------------
__global__ void gn_kernel(const float* __restrict__ x,
                          const float* __restrict__ w,
                          const float* __restrict__ bias,
                          __half* __restrict__ xn) {
    int bg = blockIdx.x;
    int b = bg >> 5, g = bg & 31;
    const float* xp = x  + ((size_t)b * CCH + g * 16) * NPIX;
    __half*      op = xn + ((size_t)b * CCH + g * 16) * NPIX;
    int tid = threadIdx.x;

    float s = 0.f, s2 = 0.f;
    for (int i = tid; i < 16 * NPIX; i += 256) {
        float v = xp[i];
        s += v; s2 += v * v;
    }
    __shared__ float red[256], red2[256];
    red[tid] = s; red2[tid] = s2;
    __syncthreads();
    for (int off = 128; off > 0; off >>= 1) {
        if (tid < off) { red[tid] += red[tid + off]; red2[tid] += red2[tid + off]; }
        __syncthreads();
    }
    float mean = red[0] * (1.f / 16384.f);
    float var  = red2[0] * (1.f / 16384.f) - mean * mean;
    float rstd = rsqrtf(var + 1e-5f);

    for (int i = tid; i < 16 * NPIX; i += 256) {
        int c = g * 16 + (i >> 10);
        op[i] = __float2half_rn((xp[i] - mean) * rstd * w[c] + bias[c]);
    }
}

__global__ void repack_kernel(const float* __restrict__ src,
                              __half* __restrict__ dst, int n) {
    int i = blockIdx.x * 256 + threadIdx.x;
    if (i < n) dst[i] = __float2half_rn(src[i]);
}

// ---------------------------------------------------------------------------
// fp16 mma helper
// ---------------------------------------------------------------------------
__device__ __forceinline__ void mma_f16(float& c0, float& c1, float& c2, float& c3,
                                        uint32_t a0, uint32_t a1, uint32_t a2, uint32_t a3,
                                        uint32_t b0, uint32_t b1) {
    asm volatile(
        "mma.sync.aligned.m16n8k16.row.col.f32.f16.f16.f32 "
        "{%0,%1,%2,%3}, {%4,%5,%6,%7}, {%8,%9}, {%0,%1,%2,%3};\n"
        : "+f"(c0), "+f"(c1), "+f"(c2), "+f"(c3)
        : "r"(a0), "r"(a1), "r"(a2), "r"(a3), "r"(b0), "r"(b1));
}

// ---------------------------------------------------------------------------
// Tile fetch/store. Tile covers 128 (m/n) x 32 (k) fp16 values, stored in SMEM
// as uint32 = fp16x2 packed along k: S[kp][m], kp in [0,16), stride 136.
// MODE 0: gmem [k][m] fp16.  MODE 1: gmem [m][k] fp16.
// ---------------------------------------------------------------------------
#define SMSTR 136

template<int MODE>
__device__ __forceinline__ void fetch_tile(const __half* __restrict__ P, int ld,
                                           int k0, int off0, int tid, uint4 v[2]) {
    if (MODE == 0) {
        // thread owns k rows 2q, 2q+1 at 8 consecutive m
        int q = tid >> 4, m8 = (tid & 15) * 8;
        v[0] = *(const uint4*)(P + (size_t)(k0 + 2 * q)     * ld + off0 + m8);
        v[1] = *(const uint4*)(P + (size_t)(k0 + 2 * q + 1) * ld + off0 + m8);
    } else {
        // thread owns row r, 16 consecutive k
        int r = tid >> 1, k16 = (tid & 1) * 16;
        v[0] = *(const uint4*)(P + (size_t)(off0 + r) * ld + k0 + k16);
        v[1] = *(const uint4*)(P + (size_t)(off0 + r) * ld + k0 + k16 + 8);
    }
}

template<int MODE>
__device__ __forceinline__ void store_tile(uint32_t* __restrict__ S, int tid,
                                           const uint4 v[2]) {
    if (MODE == 0) {
        // interleave rows 2q,2q+1 into k-pairs; 8 consecutive uint32 at [q][m8]
        int q = tid >> 4, m8 = (tid & 15) * 8;
        const uint32_t* a = (const uint32_t*)&v[0];
        const uint32_t* b = (const uint32_t*)&v[1];
        uint32_t* p = S + q * SMSTR + m8;
        #pragma unroll
        for (int i = 0; i < 4; i++) {
            p[2 * i]     = __byte_perm(a[i], b[i], 0x5410);  // lo halves -> pair
            p[2 * i + 1] = __byte_perm(a[i], b[i], 0x7632);  // hi halves -> pair
        }
    } else {
        // words are already k-pairs; scatter over 8 kp rows at column r
        int r = tid >> 1, kpb = (tid & 1) * 8;
        const uint32_t* a = (const uint32_t*)&v[0];
        const uint32_t* b = (const uint32_t*)&v[1];
        #pragma unroll
        for (int i = 0; i < 4; i++) {
            S[(kpb + i) * SMSTR + r]     = a[i];
            S[(kpb + 4 + i) * SMSTR + r] = b[i];
        }
    }
}

// ---------------------------------------------------------------------------
// Tensor-core GEMM (fp16 in, fp32 accum): C[m,n] = sum_k opA * opB.
// BM=BN=128, BK=32, 256 threads, 8 warps (2x4), warp tile 64x32,
// mma.m16n8k16, fragments 4x4 per warp, double-buffered smem.
// EPI: 0 fp32 out; 1 fp16 out + biasM[m]; 2 fp16 + fp32 dual out;
//      3 fp32 out + biasM[m] + Res[m][n]
// ---------------------------------------------------------------------------
template<int AMODE, int BMODE, int EPI>
__global__ __launch_bounds__(256)
void gemm_tc(const __half* __restrict__ A, int lda, long long strideA,
             const __half* __restrict__ B, int ldb, long long strideB,
             void* __restrict__ Cout, int ldc, long long strideC,
             int K,
             const float* __restrict__ biasM,
             const float* __restrict__ Res, long long strideRes,
             float* __restrict__ C2, long long strideC2) {
    __shared__ uint32_t As[2][16 * SMSTR];
    __shared__ uint32_t Bs[2][16 * SMSTR];

    const int tid = threadIdx.x, lane = tid & 31, w = tid >> 5;
    const int wm = w >> 2, wn = w & 3;
    const int g = lane >> 2, t = lane & 3;
    const int m0 = blockIdx.y * 128, n0 = blockIdx.x * 128;

    const __half* Ab = A + (size_t)blockIdx.z * strideA;
    const __half* Bb = B + (size_t)blockIdx.z * strideB;

    float acc[4][4][4];
    #pragma unroll
    for (int i = 0; i < 4; i++)
        #pragma unroll
        for (int j = 0; j < 4; j++)
            #pragma unroll
            for (int c = 0; c < 4; c++) acc[i][j][c] = 0.f;

    uint4 ra[2], rb[2];
    fetch_tile<AMODE>(Ab, lda, 0, m0, tid, ra);
    fetch_tile<BMODE>(Bb, ldb, 0, n0, tid, rb);
    store_tile<AMODE>(As[0], tid, ra);
    store_tile<BMODE>(Bs[0], tid, rb);
    __syncthreads();

    int cur = 0;
    for (int k0 = 0; k0 < K; k0 += 32) {
        bool has_next = (k0 + 32 < K);
        if (has_next) {
            fetch_tile<AMODE>(Ab, lda, k0 + 32, m0, tid, ra);
            fetch_tile<BMODE>(Bb, ldb, k0 + 32, n0, tid, rb);
        }

        #pragma unroll
        for (int p = 0; p < 2; p++) {          // two k16 passes (kp 0-7, 8-15)
            uint32_t af[4][4];
            uint32_t bf[4][2];
            const uint32_t* Ac  = As[cur] + (p * 8 + t) * SMSTR;
            const uint32_t* Ac4 = As[cur] + (p * 8 + t + 4) * SMSTR;
            const uint32_t* Bc  = Bs[cur] + (p * 8 + t) * SMSTR;
            const uint32_t* Bc4 = Bs[cur] + (p * 8 + t + 4) * SMSTR;
            #pragma unroll
            for (int mf = 0; mf < 4; mf++) {
                int mrow = wm * 64 + mf * 16 + g;
                af[mf][0] = Ac[mrow];
                af[mf][1] = Ac[mrow + 8];
                af[mf][2] = Ac4[mrow];
                af[mf][3] = Ac4[mrow + 8];
            }
            #pragma unroll
            for (int nf = 0; nf < 4; nf++) {
                int ncol = wn * 32 + nf * 8 + g;
                bf[nf][0] = Bc[ncol];
                bf[nf][1] = Bc4[ncol];
            }
            #pragma unroll
            for (int mf = 0; mf < 4; mf++)
                #pragma unroll
                for (int nf = 0; nf < 4; nf++)
                    mma_f16(acc[mf][nf][0], acc[mf][nf][1],
                            acc[mf][nf][2], acc[mf][nf][3],
                            af[mf][0], af[mf][1], af[mf][2], af[mf][3],
                            bf[nf][0], bf[nf][1]);
        }

        if (has_next) {
            int nxt = cur ^ 1;
            store_tile<AMODE>(As[nxt], tid, ra);
            store_tile<BMODE>(Bs[nxt], tid, rb);
            __syncthreads();
            cur = nxt;
        }
    }

    const float* Rb = (EPI == 3) ? (Res + (size_t)blockIdx.z * strideRes) : nullptr;

    #pragma unroll
    for (int mf = 0; mf < 4; mf++) {
        int m = m0 + wm * 64 + mf * 16 + g;
        float bm0 = 0.f, bm1 = 0.f;
        if (EPI == 1 || EPI == 3) { bm0 = biasM[m]; bm1 = biasM[m + 8]; }
        #pragma unroll
        for (int nf = 0; nf < 4; nf++) {
            int n = n0 + wn * 32 + nf * 8 + t * 2;
            float v0 = acc[mf][nf][0] + bm0, v1 = acc[mf][nf][1] + bm0;
            float v2 = acc[mf][nf][2] + bm1, v3 = acc[mf][nf][3] + bm1;
            if (EPI == 0) {
                float* Cb = (float*)Cout + (size_t)blockIdx.z * strideC;
                *(float2*)(Cb + (size_t)m * ldc + n)       = make_float2(v0, v1);
                *(float2*)(Cb + (size_t)(m + 8) * ldc + n) = make_float2(v2, v3);
            } else if (EPI == 1) {
                __half* Cb = (__half*)Cout + (size_t)blockIdx.z * strideC;
                *(__half2*)(Cb + (size_t)m * ldc + n)       = __floats2half2_rn(v0, v1);
                *(__half2*)(Cb + (size_t)(m + 8) * ldc + n) = __floats2half2_rn(v2, v3);
            } else if (EPI == 2) {
                __half* Cb = (__half*)Cout + (size_t)blockIdx.z * strideC;
                float*  Fb = C2 + (size_t)blockIdx.z * strideC2;
                *(__half2*)(Cb + (size_t)m * ldc + n)       = __floats2half2_rn(v0, v1);
                *(__half2*)(Cb + (size_t)(m + 8) * ldc + n) = __floats2half2_rn(v2, v3);
                *(float2*)(Fb + (size_t)m * ldc + n)        = make_float2(v0, v1);
                *(float2*)(Fb + (size_t)(m + 8) * ldc + n)  = make_float2(v2, v3);
            } else {
                float* Cb = (float*)Cout + (size_t)blockIdx.z * strideC;
                const float* r0 = Rb + (size_t)m * ldc + n;
                const float* r1 = Rb + (size_t)(m + 8) * ldc + n;
                *(float2*)(Cb + (size_t)m * ldc + n)       = make_float2(v0 + r0[0], v1 + r0[1]);
                *(float2*)(Cb + (size_t)(m + 8) * ldc + n) = make_float2(v2 + r1[0], v3 + r1[1]);
            }
        }
    }
}

// ---------------------------------------------------------------------------
// Softmax: read fp32 S, apply scale, write fp16 P
// ---------------------------------------------------------------------------
__global__ void softmax_kernel(const float* __restrict__ S,
                               __half* __restrict__ P) {
    const float* p = S + (size_t)blockIdx.x * NPIX;
    __half* q = P + (size_t)blockIdx.x * NPIX;
    int tid = threadIdx.x;
    const float scale = 0.044194173824159216f;   // 512^-0.5
    float v[4];
    float mx = -1e30f;
    #pragma unroll
    for (int i = 0; i < 4; i++) { v[i] = p[tid + i * 256] * scale; mx = fmaxf(mx, v[i]); }

    __shared__ float red[256];
    red[tid] = mx;
    __syncthreads();
    for (int off = 128; off > 0; off >>= 1) {
        if (tid < off) red[tid] = fmaxf(red[tid], red[tid + off]);
        __syncthreads();
    }
    mx = red[0];
    __syncthreads();

    float s = 0.f;
    #pragma unroll
    for (int i = 0; i < 4; i++) { v[i] = __expf(v[i] - mx); s += v[i]; }
    red[tid] = s;
    __syncthreads();
    for (int off = 128; off > 0; off >>= 1) {
        if (tid < off) red[tid] += red[tid + off];
        __syncthreads();
    }
    float inv = 1.f / red[0];
    #pragma unroll
    for (int i = 0; i < 4; i++) q[tid + i * 256] = __float2half_rn(v[i] * inv);
}

// ---------------------------------------------------------------------------
extern "C" void kernel_launch(void* const* d_in, const int* in_sizes, int n_in,
                              void* d_out, int out_size) {
    const float* x     = (const float*)d_in[0];
    const float* gnw   = (const float*)d_in[1];
    const float* gnb   = (const float*)d_in[2];
    const float* qkvw  = (const float*)d_in[3];
    const float* qkvb  = (const float*)d_in[4];
    const float* projw = (const float*)d_in[5];
    const float* projb = (const float*)d_in[6];
    float* out = (float*)d_out;

    __half *xn, *wqkv, *wprj, *qkv, *P, *Oh;
    float  *S, *Of;
    cudaGetSymbolAddress((void**)&xn,   g_xn);
    cudaGetSymbolAddress((void**)&wqkv, g_wqkv);
    cudaGetSymbolAddress((void**)&wprj, g_wprj);
    cudaGetSymbolAddress((void**)&qkv,  g_qkv);
    cudaGetSymbolAddress((void**)&S,    g_S);
    cudaGetSymbolAddress((void**)&P,    g_P);
    cudaGetSymbolAddress((void**)&Oh,   g_Oh);
    cudaGetSymbolAddress((void**)&Of,   g_Of);

    const long long sXN  = (long long)CCH * NPIX;
    const long long sQKV = (long long)3 * CCH * NPIX;
    const long long sATT = (long long)NPIX * NPIX;

    // prep: weights -> fp16, groupnorm -> fp16
    repack_kernel<<<(3 * CCH * CCH + 255) / 256, 256>>>(qkvw, wqkv, 3 * CCH * CCH);
    repack_kernel<<<(CCH * CCH + 255) / 256, 256>>>(projw, wprj, CCH * CCH);
    gn_kernel<<<NBATCH * 32, 256>>>(x, gnw, gnb, xn);

    // qkv[o][n] = W[o][c] * xn[c][n] + bias[o]   (fp16 out)
    gemm_tc<1, 0, 1><<<dim3(NPIX / 128, 1536 / 128, NBATCH), 256>>>(
        wqkv, CCH, 0,
        xn, NPIX, sXN,
        qkv, NPIX, sQKV,
        CCH, qkvb, nullptr, 0, nullptr, 0);

    // S[n][m] = q[c][n] k[c][m]  (fp32 out, scale folded into softmax)
    gemm_tc<0, 0, 0><<<dim3(NPIX / 128, NPIX / 128, NBATCH), 256>>>(
        qkv, NPIX, sQKV,
        qkv + (size_t)CCH * NPIX, NPIX, sQKV,
        S, NPIX, sATT,
        CCH, nullptr, nullptr, 0, nullptr, 0);

    // P = softmax(S * scale)  (fp16)
    softmax_kernel<<<NBATCH * NPIX, 256>>>(S, P);

    // O[c][n] = V[c][m] P[n][m]  (fp16 + fp32 dual out)
    gemm_tc<1, 1, 2><<<dim3(NPIX / 128, CCH / 128, NBATCH), 256>>>(
        qkv + (size_t)2 * CCH * NPIX, NPIX, sQKV,
        P, NPIX, sATT,
        Oh, NPIX, sXN,
        NPIX, nullptr, nullptr, 0, Of, sXN);

    // out[o][n] = Wp[o][c] Oh[c][n] + projb[o] + Of[o][n]
    gemm_tc<1, 0, 3><<<dim3(NPIX / 128, CCH / 128, NBATCH), 256>>>(
        wprj, CCH, 0,
        Oh, NPIX, sXN,
        out, NPIX, sXN,
        CCH, projb, Of, sXN, nullptr, 0);
}

// round 7
// speedup vs baseline: 6.2958x; 1.3429x over previous
#include <cuda_runtime.h>
#include <cuda_fp16.h>
#include <math.h>
#include <stdint.h>

// Problem: x [16,512,32,32] -> B=16, C=512, N=1024
#define NBATCH 16
#define CCH    512
#define NPIX   1024

// ---------------------------------------------------------------------------
// Scratch (__device__ globals; no allocation allowed)
// ---------------------------------------------------------------------------
__device__ __half g_xn  [NBATCH * CCH * NPIX];        // fp16 [b][c][n]
__device__ __half g_wqkv[3 * CCH * CCH];              // fp16 qkv weight
__device__ __half g_wprj[CCH * CCH];                  // fp16 proj weight
__device__ __half g_qkv [NBATCH * 3 * CCH * NPIX];    // fp16 [b][o][n]
__device__ float  g_S   [NBATCH * NPIX * NPIX];       // fp32 scores
__device__ __half g_P   [NBATCH * NPIX * NPIX];       // fp16 probs
__device__ __half g_Oh  [NBATCH * CCH * NPIX];        // fp16 attn out
__device__ float  g_Of  [NBATCH * CCH * NPIX];        // fp32 attn out (residual)

__device__ __forceinline__ uint32_t smem_u32(const void* p) {
    uint32_t a;
    asm("{ .reg .u64 t; cvta.to.shared.u64 t, %1; cvt.u32.u64 %0, t; }"
        : "=r"(a) : "l"(p));
    return a;
}

// ---------------------------------------------------------------------------
// GroupNorm -> fp16 xn [b][c][n]
// ---------------------------------------------------------------------------
__global__ void gn_kernel(const float* __restrict__ x,
                          const float* __restrict__ w,
                          const float* __restrict__ bias,
                          __half* __restrict__ xn) {
    int bg = blockIdx.x;
    int b = bg >> 5, g = bg & 31;
    const float* xp = x  + ((size_t)b * CCH + g * 16) * NPIX;
    __half*      op = xn + ((size_t)b * CCH + g * 16) * NPIX;
    int tid = threadIdx.x;

    float s = 0.f, s2 = 0.f;
    for (int i = tid; i < 16 * NPIX; i += 256) {
        float v = xp[i];
        s += v; s2 += v * v;
    }
    __shared__ float red[256], red2[256];
    red[tid] = s; red2[tid] = s2;
    __syncthreads();
    for (int off = 128; off > 0; off >>= 1) {
        if (tid < off) { red[tid] += red[tid + off]; red2[tid] += red2[tid + off]; }
        __syncthreads();
    }
    float mean = red[0] * (1.f / 16384.f);
    float var  = red2[0] * (1.f / 16384.f) - mean * mean;
    float rstd = rsqrtf(var + 1e-5f);

    for (int i = tid; i < 16 * NPIX; i += 256) {
        int c = g * 16 + (i >> 10);
        op[i] = __float2half_rn((xp[i] - mean) * rstd * w[c] + bias[c]);
    }
}

__global__ void repack_kernel(const float* __restrict__ src,
                              __half* __restrict__ dst, int n) {
    int i = blockIdx.x * 256 + threadIdx.x;
    if (i < n) dst[i] = __float2half_rn(src[i]);
}

// ---------------------------------------------------------------------------
// mma / ldmatrix / cp.async helpers
// ---------------------------------------------------------------------------
__device__ __forceinline__ void mma_f16(float& c0, float& c1, float& c2, float& c3,
                                        uint32_t a0, uint32_t a1, uint32_t a2, uint32_t a3,
                                        uint32_t b0, uint32_t b1) {
    asm volatile(
        "mma.sync.aligned.m16n8k16.row.col.f32.f16.f16.f32 "
        "{%0,%1,%2,%3}, {%4,%5,%6,%7}, {%8,%9}, {%0,%1,%2,%3};\n"
        : "+f"(c0), "+f"(c1), "+f"(c2), "+f"(c3)
        : "r"(a0), "r"(a1), "r"(a2), "r"(a3), "r"(b0), "r"(b1));
}

__device__ __forceinline__ void ldsm_x4(uint32_t& r0, uint32_t& r1,
                                        uint32_t& r2, uint32_t& r3, uint32_t a) {
    asm volatile("ldmatrix.sync.aligned.m8n8.x4.shared.b16 {%0,%1,%2,%3}, [%4];"
                 : "=r"(r0), "=r"(r1), "=r"(r2), "=r"(r3) : "r"(a));
}
__device__ __forceinline__ void ldsm_x4_t(uint32_t& r0, uint32_t& r1,
                                          uint32_t& r2, uint32_t& r3, uint32_t a) {
    asm volatile("ldmatrix.sync.aligned.m8n8.x4.trans.shared.b16 {%0,%1,%2,%3}, [%4];"
                 : "=r"(r0), "=r"(r1), "=r"(r2), "=r"(r3) : "r"(a));
}

#define CP_ASYNC16(dst, src) \
    asm volatile("cp.async.cg.shared.global [%0], [%1], 16;" :: "r"(dst), "l"(src))
#define CP_COMMIT() asm volatile("cp.async.commit_group;" ::: "memory")
#define CP_WAIT1()  asm volatile("cp.async.wait_group 1;" ::: "memory")

// ---------------------------------------------------------------------------
// SMEM tiles: one stage = A tile (8KB) + B tile (8KB), BK = 32.
// MODE 0: gmem [k][m] -> smem [k][m], 32 rows x 256B (16 chunks of 16B),
//         chunk swizzle c ^= (k & 7)      -> ldmatrix .trans, conflict-free.
// MODE 1: gmem [m][k] -> smem [m][k], 128 rows x 64B (4 chunks),
//         chunk swizzle c ^= ((m>>1) & 3) -> ldmatrix non-trans, conflict-free.
// ---------------------------------------------------------------------------
template<int MODE>
__device__ __forceinline__ void fetch_stage(const __half* __restrict__ Pg, int ld,
                                            int k0, int off0, int tid, uint32_t sbase) {
    #pragma unroll
    for (int i = 0; i < 2; i++) {
        int id = tid + 256 * i;
        if (MODE == 0) {
            int k = id >> 4, c = id & 15;
            const __half* src = Pg + (size_t)(k0 + k) * ld + off0 + c * 8;
            uint32_t dst = sbase + k * 256 + ((c ^ (k & 7)) << 4);
            CP_ASYNC16(dst, src);
        } else {
            int m = id >> 2, c = id & 3;
            const __half* src = Pg + (size_t)(off0 + m) * ld + k0 + c * 8;
            uint32_t dst = sbase + m * 64 + ((c ^ ((m >> 1) & 3)) << 4);
            CP_ASYNC16(dst, src);
        }
    }
}

// fragment addresses (per-warp tile offsets wm*64 rows / wn*32 cols)
template<int MODE>
__device__ __forceinline__ uint32_t fragA_addr(uint32_t base, int lane, int wm,
                                               int mf, int p) {
    if (MODE == 0) {
        int k_l  = p * 16 + (lane & 7) + ((lane >> 4) & 1) * 8;
        int moff = wm * 64 + mf * 16 + ((lane >> 3) & 1) * 8;
        int c = moff >> 3;
        return base + k_l * 256 + ((c ^ (k_l & 7)) << 4);
    } else {
        int m_l = wm * 64 + mf * 16 + (lane & 15);
        int c   = p * 2 + (lane >> 4);
        return base + m_l * 64 + ((c ^ ((m_l >> 1) & 3)) << 4);
    }
}
template<int MODE>
__device__ __forceinline__ uint32_t fragB_addr(uint32_t base, int lane, int wn,
                                               int nf0, int p) {
    if (MODE == 0) {
        int k_l  = p * 16 + (lane & 7) + ((lane >> 3) & 1) * 8;
        int noff = wn * 32 + nf0 * 8 + ((lane >> 4) & 1) * 8;
        int c = noff >> 3;
        return base + k_l * 256 + ((c ^ (k_l & 7)) << 4);
    } else {
        int n_l = wn * 32 + nf0 * 8 + (lane & 7) + ((lane >> 4) & 1) * 8;
        int c   = p * 2 + ((lane >> 3) & 1);
        return base + n_l * 64 + ((c ^ ((n_l >> 1) & 3)) << 4);
    }
}

// ---------------------------------------------------------------------------
// Tensor-core GEMM (fp16 in, fp32 accum): C[m,n] = sum_k opA * opB.
// BM=BN=128, BK=32, 256 threads, 8 warps (2x4), warp tile 64x32,
// cp.async 3-stage + ldmatrix fragments.
// EPI: 0 fp32 out; 1 fp16 out + biasM[m]; 2 fp16 + fp32 dual out;
//      3 fp32 out + biasM[m] + Res[m][n]
// ---------------------------------------------------------------------------
template<int AMODE, int BMODE, int EPI>
__global__ __launch_bounds__(256)
void gemm_tc(const __half* __restrict__ A, int lda, long long strideA,
             const __half* __restrict__ B, int ldb, long long strideB,
             void* __restrict__ Cout, int ldc, long long strideC,
             int K,
             const float* __restrict__ biasM,
             const float* __restrict__ Res, long long strideRes,
             float* __restrict__ C2, long long strideC2) {
    __shared__ uint8_t sA[3][8192];
    __shared__ uint8_t sB[3][8192];

    const int tid = threadIdx.x, lane = tid & 31, w = tid >> 5;
    const int wm = w >> 2, wn = w & 3;
    const int g = lane >> 2, t = lane & 3;
    const int m0 = blockIdx.y * 128, n0 = blockIdx.x * 128;

    const __half* Ab = A + (size_t)blockIdx.z * strideA;
    const __half* Bb = B + (size_t)blockIdx.z * strideB;

    uint32_t baseA[3], baseB[3];
    #pragma unroll
    for (int s = 0; s < 3; s++) {
        baseA[s] = smem_u32(sA[s]);
        baseB[s] = smem_u32(sB[s]);
    }

    float acc[4][4][4];
    #pragma unroll
    for (int i = 0; i < 4; i++)
        #pragma unroll
        for (int j = 0; j < 4; j++)
            #pragma unroll
            for (int c = 0; c < 4; c++) acc[i][j][c] = 0.f;

    const int nch = K >> 5;

    // prologue: stages 0,1
    fetch_stage<AMODE>(Ab, lda, 0, m0, tid, baseA[0]);
    fetch_stage<BMODE>(Bb, ldb, 0, n0, tid, baseB[0]);
    CP_COMMIT();
    fetch_stage<AMODE>(Ab, lda, 32, m0, tid, baseA[1]);
    fetch_stage<BMODE>(Bb, ldb, 32, n0, tid, baseB[1]);
    CP_COMMIT();

    int s = 0;
    for (int ch = 0; ch < nch; ch++) {
        CP_WAIT1();
        __syncthreads();

        if (ch + 2 < nch) {
            int sn = (s + 2 >= 3) ? s - 1 : s + 2;
            fetch_stage<AMODE>(Ab, lda, (ch + 2) * 32, m0, tid, baseA[sn]);
            fetch_stage<BMODE>(Bb, ldb, (ch + 2) * 32, n0, tid, baseB[sn]);
        }
        CP_COMMIT();

        #pragma unroll
        for (int p = 0; p < 2; p++) {
            uint32_t af[4][4];
            uint32_t bf[4][2];
            #pragma unroll
            for (int mf = 0; mf < 4; mf++) {
                uint32_t a = fragA_addr<AMODE>(baseA[s], lane, wm, mf, p);
                if (AMODE == 0)
                    ldsm_x4_t(af[mf][0], af[mf][1], af[mf][2], af[mf][3], a);
                else
                    ldsm_x4(af[mf][0], af[mf][1], af[mf][2], af[mf][3], a);
            }
            #pragma unroll
            for (int nf0 = 0; nf0 < 4; nf0 += 2) {
                uint32_t a = fragB_addr<BMODE>(baseB[s], lane, wn, nf0, p);
                if (BMODE == 0)
                    ldsm_x4_t(bf[nf0][0], bf[nf0][1], bf[nf0 + 1][0], bf[nf0 + 1][1], a);
                else
                    ldsm_x4(bf[nf0][0], bf[nf0][1], bf[nf0 + 1][0], bf[nf0 + 1][1], a);
            }
            #pragma unroll
            for (int mf = 0; mf < 4; mf++)
                #pragma unroll
                for (int nf = 0; nf < 4; nf++)
                    mma_f16(acc[mf][nf][0], acc[mf][nf][1],
                            acc[mf][nf][2], acc[mf][nf][3],
                            af[mf][0], af[mf][1], af[mf][2], af[mf][3],
                            bf[nf][0], bf[nf][1]);
        }
        __syncthreads();
        s = (s + 1 >= 3) ? 0 : s + 1;
    }

    const float* Rb = (EPI == 3) ? (Res + (size_t)blockIdx.z * strideRes) : nullptr;

    #pragma unroll
    for (int mf = 0; mf < 4; mf++) {
        int m = m0 + wm * 64 + mf * 16 + g;
        float bm0 = 0.f, bm1 = 0.f;
        if (EPI == 1 || EPI == 3) { bm0 = biasM[m]; bm1 = biasM[m + 8]; }
        #pragma unroll
        for (int nf = 0; nf < 4; nf++) {
            int n = n0 + wn * 32 + nf * 8 + t * 2;
            float v0 = acc[mf][nf][0] + bm0, v1 = acc[mf][nf][1] + bm0;
            float v2 = acc[mf][nf][2] + bm1, v3 = acc[mf][nf][3] + bm1;
            if (EPI == 0) {
                float* Cb = (float*)Cout + (size_t)blockIdx.z * strideC;
                *(float2*)(Cb + (size_t)m * ldc + n)       = make_float2(v0, v1);
                *(float2*)(Cb + (size_t)(m + 8) * ldc + n) = make_float2(v2, v3);
            } else if (EPI == 1) {
                __half* Cb = (__half*)Cout + (size_t)blockIdx.z * strideC;
                *(__half2*)(Cb + (size_t)m * ldc + n)       = __floats2half2_rn(v0, v1);
                *(__half2*)(Cb + (size_t)(m + 8) * ldc + n) = __floats2half2_rn(v2, v3);
            } else if (EPI == 2) {
                __half* Cb = (__half*)Cout + (size_t)blockIdx.z * strideC;
                float*  Fb = C2 + (size_t)blockIdx.z * strideC2;
                *(__half2*)(Cb + (size_t)m * ldc + n)       = __floats2half2_rn(v0, v1);
                *(__half2*)(Cb + (size_t)(m + 8) * ldc + n) = __floats2half2_rn(v2, v3);
                *(float2*)(Fb + (size_t)m * ldc + n)        = make_float2(v0, v1);
                *(float2*)(Fb + (size_t)(m + 8) * ldc + n)  = make_float2(v2, v3);
            } else {
                float* Cb = (float*)Cout + (size_t)blockIdx.z * strideC;
                const float* r0 = Rb + (size_t)m * ldc + n;
                const float* r1 = Rb + (size_t)(m + 8) * ldc + n;
                *(float2*)(Cb + (size_t)m * ldc + n)       = make_float2(v0 + r0[0], v1 + r0[1]);
                *(float2*)(Cb + (size_t)(m + 8) * ldc + n) = make_float2(v2 + r1[0], v3 + r1[1]);
            }
        }
    }
}

// ---------------------------------------------------------------------------
// Softmax: read fp32 S, apply scale, write fp16 P
// ---------------------------------------------------------------------------
__global__ void softmax_kernel(const float* __restrict__ S,
                               __half* __restrict__ P) {
    const float* p = S + (size_t)blockIdx.x * NPIX;
    __half* q = P + (size_t)blockIdx.x * NPIX;
    int tid = threadIdx.x;
    const float scale = 0.044194173824159216f;   // 512^-0.5
    float v[4];
    float mx = -1e30f;
    #pragma unroll
    for (int i = 0; i < 4; i++) { v[i] = p[tid + i * 256] * scale; mx = fmaxf(mx, v[i]); }

    __shared__ float red[256];
    red[tid] = mx;
    __syncthreads();
    for (int off = 128; off > 0; off >>= 1) {
        if (tid < off) red[tid] = fmaxf(red[tid], red[tid + off]);
        __syncthreads();
    }
    mx = red[0];
    __syncthreads();

    float s = 0.f;
    #pragma unroll
    for (int i = 0; i < 4; i++) { v[i] = __expf(v[i] - mx); s += v[i]; }
    red[tid] = s;
    __syncthreads();
    for (int off = 128; off > 0; off >>= 1) {
        if (tid < off) red[tid] += red[tid + off];
        __syncthreads();
    }
    float inv = 1.f / red[0];
    #pragma unroll
    for (int i = 0; i < 4; i++) q[tid + i * 256] = __float2half_rn(v[i] * inv);
}

// ---------------------------------------------------------------------------
extern "C" void kernel_launch(void* const* d_in, const int* in_sizes, int n_in,
                              void* d_out, int out_size) {
    const float* x     = (const float*)d_in[0];
    const float* gnw   = (const float*)d_in[1];
    const float* gnb   = (const float*)d_in[2];
    const float* qkvw  = (const float*)d_in[3];
    const float* qkvb  = (const float*)d_in[4];
    const float* projw = (const float*)d_in[5];
    const float* projb = (const float*)d_in[6];
    float* out = (float*)d_out;

    __half *xn, *wqkv, *wprj, *qkv, *P, *Oh;
    float  *S, *Of;
    cudaGetSymbolAddress((void**)&xn,   g_xn);
    cudaGetSymbolAddress((void**)&wqkv, g_wqkv);
    cudaGetSymbolAddress((void**)&wprj, g_wprj);
    cudaGetSymbolAddress((void**)&qkv,  g_qkv);
    cudaGetSymbolAddress((void**)&S,    g_S);
    cudaGetSymbolAddress((void**)&P,    g_P);
    cudaGetSymbolAddress((void**)&Oh,   g_Oh);
    cudaGetSymbolAddress((void**)&Of,   g_Of);

    const long long sXN  = (long long)CCH * NPIX;
    const long long sQKV = (long long)3 * CCH * NPIX;
    const long long sATT = (long long)NPIX * NPIX;

    // prep: weights -> fp16, groupnorm -> fp16
    repack_kernel<<<(3 * CCH * CCH + 255) / 256, 256>>>(qkvw, wqkv, 3 * CCH * CCH);
    repack_kernel<<<(CCH * CCH + 255) / 256, 256>>>(projw, wprj, CCH * CCH);
    gn_kernel<<<NBATCH * 32, 256>>>(x, gnw, gnb, xn);

    // qkv[o][n] = W[o][c] * xn[c][n] + bias[o]   (fp16 out)
    gemm_tc<1, 0, 1><<<dim3(NPIX / 128, 1536 / 128, NBATCH), 256>>>(
        wqkv, CCH, 0,
        xn, NPIX, sXN,
        qkv, NPIX, sQKV,
        CCH, qkvb, nullptr, 0, nullptr, 0);

    // S[n][m] = q[c][n] k[c][m]  (fp32 out, scale folded into softmax)
    gemm_tc<0, 0, 0><<<dim3(NPIX / 128, NPIX / 128, NBATCH), 256>>>(
        qkv, NPIX, sQKV,
        qkv + (size_t)CCH * NPIX, NPIX, sQKV,
        S, NPIX, sATT,
        CCH, nullptr, nullptr, 0, nullptr, 0);

    // P = softmax(S * scale)  (fp16)
    softmax_kernel<<<NBATCH * NPIX, 256>>>(S, P);

    // O[c][n] = V[c][m] P[n][m]  (fp16 + fp32 dual out)
    gemm_tc<1, 1, 2><<<dim3(NPIX / 128, CCH / 128, NBATCH), 256>>>(
        qkv + (size_t)2 * CCH * NPIX, NPIX, sQKV,
        P, NPIX, sATT,
        Oh, NPIX, sXN,
        NPIX, nullptr, nullptr, 0, Of, sXN);

    // out[o][n] = Wp[o][c] Oh[c][n] + projb[o] + Of[o][n]
    gemm_tc<1, 0, 3><<<dim3(NPIX / 128, CCH / 128, NBATCH), 256>>>(
        wprj, CCH, 0,
        Oh, NPIX, sXN,
        out, NPIX, sXN,
        CCH, projb, Of, sXN, nullptr, 0);
}

// round 8
// speedup vs baseline: 6.6553x; 1.0571x over previous
#include <cuda_runtime.h>
#include <cuda_fp16.h>
#include <math.h>
#include <stdint.h>

// Problem: x [16,512,32,32] -> B=16, C=512, N=1024
#define NBATCH 16
#define CCH    512
#define NPIX   1024

// ---------------------------------------------------------------------------
// Scratch (__device__ globals; no allocation allowed)
// ---------------------------------------------------------------------------
__device__ __half g_xn  [NBATCH * CCH * NPIX];        // fp16 [b][c][n]
__device__ __half g_wqkv[3 * CCH * CCH];              // fp16 qkv weight
__device__ __half g_wprj[CCH * CCH];                  // fp16 proj weight
__device__ __half g_qkv [NBATCH * 3 * CCH * NPIX];    // fp16 [b][o][n]
__device__ float  g_S   [NBATCH * NPIX * NPIX];       // fp32 scores
__device__ __half g_P   [NBATCH * NPIX * NPIX];       // fp16 probs
__device__ __half g_Oh  [NBATCH * CCH * NPIX];        // fp16 attn out
__device__ float  g_Of  [NBATCH * CCH * NPIX];        // fp32 attn out (residual)

__device__ __forceinline__ uint32_t smem_u32(const void* p) {
    uint32_t a;
    asm("{ .reg .u64 t; cvta.to.shared.u64 t, %1; cvt.u32.u64 %0, t; }"
        : "=r"(a) : "l"(p));
    return a;
}

// ---------------------------------------------------------------------------
// GroupNorm -> fp16 xn [b][c][n]
// ---------------------------------------------------------------------------
__global__ void gn_kernel(const float* __restrict__ x,
                          const float* __restrict__ w,
                          const float* __restrict__ bias,
                          __half* __restrict__ xn) {
    int bg = blockIdx.x;
    int b = bg >> 5, g = bg & 31;
    const float* xp = x  + ((size_t)b * CCH + g * 16) * NPIX;
    __half*      op = xn + ((size_t)b * CCH + g * 16) * NPIX;
    int tid = threadIdx.x;

    float s = 0.f, s2 = 0.f;
    for (int i = tid; i < 16 * NPIX; i += 256) {
        float v = xp[i];
        s += v; s2 += v * v;
    }
    __shared__ float red[256], red2[256];
    red[tid] = s; red2[tid] = s2;
    __syncthreads();
    for (int off = 128; off > 0; off >>= 1) {
        if (tid < off) { red[tid] += red[tid + off]; red2[tid] += red2[tid + off]; }
        __syncthreads();
    }
    float mean = red[0] * (1.f / 16384.f);
    float var  = red2[0] * (1.f / 16384.f) - mean * mean;
    float rstd = rsqrtf(var + 1e-5f);

    for (int i = tid; i < 16 * NPIX; i += 256) {
        int c = g * 16 + (i >> 10);
        op[i] = __float2half_rn((xp[i] - mean) * rstd * w[c] + bias[c]);
    }
}

__global__ void repack_kernel(const float* __restrict__ src,
                              __half* __restrict__ dst, int n) {
    int i = blockIdx.x * 256 + threadIdx.x;
    if (i < n) dst[i] = __float2half_rn(src[i]);
}

// ---------------------------------------------------------------------------
// mma / ldmatrix / cp.async helpers
// ---------------------------------------------------------------------------
__device__ __forceinline__ void mma_f16(float& c0, float& c1, float& c2, float& c3,
                                        uint32_t a0, uint32_t a1, uint32_t a2, uint32_t a3,
                                        uint32_t b0, uint32_t b1) {
    asm volatile(
        "mma.sync.aligned.m16n8k16.row.col.f32.f16.f16.f32 "
        "{%0,%1,%2,%3}, {%4,%5,%6,%7}, {%8,%9}, {%0,%1,%2,%3};\n"
        : "+f"(c0), "+f"(c1), "+f"(c2), "+f"(c3)
        : "r"(a0), "r"(a1), "r"(a2), "r"(a3), "r"(b0), "r"(b1));
}

__device__ __forceinline__ void ldsm_x4(uint32_t& r0, uint32_t& r1,
                                        uint32_t& r2, uint32_t& r3, uint32_t a) {
    asm volatile("ldmatrix.sync.aligned.m8n8.x4.shared.b16 {%0,%1,%2,%3}, [%4];"
                 : "=r"(r0), "=r"(r1), "=r"(r2), "=r"(r3) : "r"(a));
}
__device__ __forceinline__ void ldsm_x4_t(uint32_t& r0, uint32_t& r1,
                                          uint32_t& r2, uint32_t& r3, uint32_t a) {
    asm volatile("ldmatrix.sync.aligned.m8n8.x4.trans.shared.b16 {%0,%1,%2,%3}, [%4];"
                 : "=r"(r0), "=r"(r1), "=r"(r2), "=r"(r3) : "r"(a));
}

#define CP_ASYNC16(dst, src) \
    asm volatile("cp.async.cg.shared.global [%0], [%1], 16;" :: "r"(dst), "l"(src))
#define CP_COMMIT() asm volatile("cp.async.commit_group;" ::: "memory")
#define CP_WAIT1()  asm volatile("cp.async.wait_group 1;" ::: "memory")

// ---------------------------------------------------------------------------
// SMEM tiles: one stage = A tile (8KB) + B tile (8KB), BK = 32.
// MODE 0: gmem [k][m] -> smem [k][m], 32 rows x 256B (16 chunks of 16B),
//         chunk swizzle c ^= (k & 7)      -> ldmatrix .trans, conflict-free.
// MODE 1: gmem [m][k] -> smem [m][k], 128 rows x 64B (4 chunks),
//         chunk swizzle c ^= ((m>>1) & 3) -> ldmatrix non-trans, conflict-free.
// ---------------------------------------------------------------------------
template<int MODE>
__device__ __forceinline__ void fetch_stage(const __half* __restrict__ Pg, int ld,
                                            int k0, int off0, int tid, uint32_t sbase) {
    #pragma unroll
    for (int i = 0; i < 2; i++) {
        int id = tid + 256 * i;
        if (MODE == 0) {
            int k = id >> 4, c = id & 15;
            const __half* src = Pg + (size_t)(k0 + k) * ld + off0 + c * 8;
            uint32_t dst = sbase + k * 256 + ((c ^ (k & 7)) << 4);
            CP_ASYNC16(dst, src);
        } else {
            int m = id >> 2, c = id & 3;
            const __half* src = Pg + (size_t)(off0 + m) * ld + k0 + c * 8;
            uint32_t dst = sbase + m * 64 + ((c ^ ((m >> 1) & 3)) << 4);
            CP_ASYNC16(dst, src);
        }
    }
}

// fragment addresses (per-warp tile offsets wm*64 rows / wn*32 cols)
template<int MODE>
__device__ __forceinline__ uint32_t fragA_addr(uint32_t base, int lane, int wm,
                                               int mf, int p) {
    if (MODE == 0) {
        int k_l  = p * 16 + (lane & 7) + ((lane >> 4) & 1) * 8;
        int moff = wm * 64 + mf * 16 + ((lane >> 3) & 1) * 8;
        int c = moff >> 3;
        return base + k_l * 256 + ((c ^ (k_l & 7)) << 4);
    } else {
        int m_l = wm * 64 + mf * 16 + (lane & 15);
        int c   = p * 2 + (lane >> 4);
        return base + m_l * 64 + ((c ^ ((m_l >> 1) & 3)) << 4);
    }
}
template<int MODE>
__device__ __forceinline__ uint32_t fragB_addr(uint32_t base, int lane, int wn,
                                               int nf0, int p) {
    if (MODE == 0) {
        int k_l  = p * 16 + (lane & 7) + ((lane >> 3) & 1) * 8;
        int noff = wn * 32 + nf0 * 8 + ((lane >> 4) & 1) * 8;
        int c = noff >> 3;
        return base + k_l * 256 + ((c ^ (k_l & 7)) << 4);
    } else {
        int n_l = wn * 32 + nf0 * 8 + (lane & 7) + ((lane >> 4) & 1) * 8;
        int c   = p * 2 + ((lane >> 3) & 1);
        return base + n_l * 64 + ((c ^ ((n_l >> 1) & 3)) << 4);
    }
}

// ---------------------------------------------------------------------------
// Tensor-core GEMM (fp16 in, fp32 accum): C[m,n] = sum_k opA * opB.
// BM=BN=128, BK=32, 256 threads, 8 warps (2x4), warp tile 64x32,
// cp.async 3-stage + ldmatrix, ONE __syncthreads per k-chunk.
// EPI: 0 fp32 out; 1 fp16 out + biasM[m]; 2 fp16 + fp32 dual out;
//      3 fp32 out + biasM[m] + Res[m][n]
// ---------------------------------------------------------------------------
template<int AMODE, int BMODE, int EPI>
__global__ __launch_bounds__(256)
void gemm_tc(const __half* __restrict__ A, int lda, long long strideA,
             const __half* __restrict__ B, int ldb, long long strideB,
             void* __restrict__ Cout, int ldc, long long strideC,
             int K,
             const float* __restrict__ biasM,
             const float* __restrict__ Res, long long strideRes,
             float* __restrict__ C2, long long strideC2) {
    __shared__ uint8_t sA[3][8192];
    __shared__ uint8_t sB[3][8192];

    const int tid = threadIdx.x, lane = tid & 31, w = tid >> 5;
    const int wm = w >> 2, wn = w & 3;
    const int g = lane >> 2, t = lane & 3;
    const int m0 = blockIdx.y * 128, n0 = blockIdx.x * 128;

    const __half* Ab = A + (size_t)blockIdx.z * strideA;
    const __half* Bb = B + (size_t)blockIdx.z * strideB;

    uint32_t baseA[3], baseB[3];
    #pragma unroll
    for (int s = 0; s < 3; s++) {
        baseA[s] = smem_u32(sA[s]);
        baseB[s] = smem_u32(sB[s]);
    }

    float acc[4][4][4];
    #pragma unroll
    for (int i = 0; i < 4; i++)
        #pragma unroll
        for (int j = 0; j < 4; j++)
            #pragma unroll
            for (int c = 0; c < 4; c++) acc[i][j][c] = 0.f;

    const int nch = K >> 5;

    // prologue: stages 0,1
    fetch_stage<AMODE>(Ab, lda, 0, m0, tid, baseA[0]);
    fetch_stage<BMODE>(Bb, ldb, 0, n0, tid, baseB[0]);
    CP_COMMIT();
    fetch_stage<AMODE>(Ab, lda, 32, m0, tid, baseA[1]);
    fetch_stage<BMODE>(Bb, ldb, 32, n0, tid, baseB[1]);
    CP_COMMIT();

    int s = 0;
    for (int ch = 0; ch < nch; ch++) {
        CP_WAIT1();
        __syncthreads();   // all warps done consuming the stage we're about to refill

        if (ch + 2 < nch) {
            int sn = (s + 2 >= 3) ? s - 1 : s + 2;
            fetch_stage<AMODE>(Ab, lda, (ch + 2) * 32, m0, tid, baseA[sn]);
            fetch_stage<BMODE>(Bb, ldb, (ch + 2) * 32, n0, tid, baseB[sn]);
        }
        CP_COMMIT();

        #pragma unroll
        for (int p = 0; p < 2; p++) {
            uint32_t af[4][4];
            uint32_t bf[4][2];
            #pragma unroll
            for (int nf0 = 0; nf0 < 4; nf0 += 2) {
                uint32_t a = fragB_addr<BMODE>(baseB[s], lane, wn, nf0, p);
                if (BMODE == 0)
                    ldsm_x4_t(bf[nf0][0], bf[nf0][1], bf[nf0 + 1][0], bf[nf0 + 1][1], a);
                else
                    ldsm_x4(bf[nf0][0], bf[nf0][1], bf[nf0 + 1][0], bf[nf0 + 1][1], a);
            }
            #pragma unroll
            for (int mf = 0; mf < 4; mf++) {
                uint32_t a = fragA_addr<AMODE>(baseA[s], lane, wm, mf, p);
                if (AMODE == 0)
                    ldsm_x4_t(af[mf][0], af[mf][1], af[mf][2], af[mf][3], a);
                else
                    ldsm_x4(af[mf][0], af[mf][1], af[mf][2], af[mf][3], a);
            }
            #pragma unroll
            for (int mf = 0; mf < 4; mf++)
                #pragma unroll
                for (int nf = 0; nf < 4; nf++)
                    mma_f16(acc[mf][nf][0], acc[mf][nf][1],
                            acc[mf][nf][2], acc[mf][nf][3],
                            af[mf][0], af[mf][1], af[mf][2], af[mf][3],
                            bf[nf][0], bf[nf][1]);
        }
        // no trailing barrier: next iteration's sync (after its wait_group)
        // guarantees stage s is fully consumed before any warp refills it.
        s = (s + 1 >= 3) ? 0 : s + 1;
    }

    const float* Rb = (EPI == 3) ? (Res + (size_t)blockIdx.z * strideRes) : nullptr;

    #pragma unroll
    for (int mf = 0; mf < 4; mf++) {
        int m = m0 + wm * 64 + mf * 16 + g;
        float bm0 = 0.f, bm1 = 0.f;
        if (EPI == 1 || EPI == 3) { bm0 = biasM[m]; bm1 = biasM[m + 8]; }
        #pragma unroll
        for (int nf = 0; nf < 4; nf++) {
            int n = n0 + wn * 32 + nf * 8 + t * 2;
            float v0 = acc[mf][nf][0] + bm0, v1 = acc[mf][nf][1] + bm0;
            float v2 = acc[mf][nf][2] + bm1, v3 = acc[mf][nf][3] + bm1;
            if (EPI == 0) {
                float* Cb = (float*)Cout + (size_t)blockIdx.z * strideC;
                *(float2*)(Cb + (size_t)m * ldc + n)       = make_float2(v0, v1);
                *(float2*)(Cb + (size_t)(m + 8) * ldc + n) = make_float2(v2, v3);
            } else if (EPI == 1) {
                __half* Cb = (__half*)Cout + (size_t)blockIdx.z * strideC;
                *(__half2*)(Cb + (size_t)m * ldc + n)       = __floats2half2_rn(v0, v1);
                *(__half2*)(Cb + (size_t)(m + 8) * ldc + n) = __floats2half2_rn(v2, v3);
            } else if (EPI == 2) {
                __half* Cb = (__half*)Cout + (size_t)blockIdx.z * strideC;
                float*  Fb = C2 + (size_t)blockIdx.z * strideC2;
                *(__half2*)(Cb + (size_t)m * ldc + n)       = __floats2half2_rn(v0, v1);
                *(__half2*)(Cb + (size_t)(m + 8) * ldc + n) = __floats2half2_rn(v2, v3);
                *(float2*)(Fb + (size_t)m * ldc + n)        = make_float2(v0, v1);
                *(float2*)(Fb + (size_t)(m + 8) * ldc + n)  = make_float2(v2, v3);
            } else {
                float* Cb = (float*)Cout + (size_t)blockIdx.z * strideC;
                const float* r0 = Rb + (size_t)m * ldc + n;
                const float* r1 = Rb + (size_t)(m + 8) * ldc + n;
                *(float2*)(Cb + (size_t)m * ldc + n)       = make_float2(v0 + r0[0], v1 + r0[1]);
                *(float2*)(Cb + (size_t)(m + 8) * ldc + n) = make_float2(v2 + r1[0], v3 + r1[1]);
            }
        }
    }
}

// ---------------------------------------------------------------------------
// Softmax: float4 loads, shuffle reductions, fp16 output
// ---------------------------------------------------------------------------
__global__ void softmax_kernel(const float* __restrict__ S,
                               __half* __restrict__ P) {
    const float4* p = (const float4*)(S + (size_t)blockIdx.x * NPIX);
    __half2* q = (__half2*)(P + (size_t)blockIdx.x * NPIX);
    const int tid = threadIdx.x, lane = tid & 31, wid = tid >> 5;
    const float scale = 0.044194173824159216f;   // 512^-0.5
    __shared__ float wred[8];

    float4 v = p[tid];
    v.x *= scale; v.y *= scale; v.z *= scale; v.w *= scale;

    float mx = fmaxf(fmaxf(v.x, v.y), fmaxf(v.z, v.w));
    #pragma unroll
    for (int off = 16; off > 0; off >>= 1)
        mx = fmaxf(mx, __shfl_xor_sync(0xFFFFFFFFu, mx, off));
    if (lane == 0) wred[wid] = mx;
    __syncthreads();
    mx = wred[0];
    #pragma unroll
    for (int i = 1; i < 8; i++) mx = fmaxf(mx, wred[i]);
    __syncthreads();

    v.x = __expf(v.x - mx); v.y = __expf(v.y - mx);
    v.z = __expf(v.z - mx); v.w = __expf(v.w - mx);
    float s = (v.x + v.y) + (v.z + v.w);
    #pragma unroll
    for (int off = 16; off > 0; off >>= 1)
        s += __shfl_xor_sync(0xFFFFFFFFu, s, off);
    if (lane == 0) wred[wid] = s;
    __syncthreads();
    s = wred[0];
    #pragma unroll
    for (int i = 1; i < 8; i++) s += wred[i];
    float inv = 1.f / s;

    q[2 * tid]     = __floats2half2_rn(v.x * inv, v.y * inv);
    q[2 * tid + 1] = __floats2half2_rn(v.z * inv, v.w * inv);
}

// ---------------------------------------------------------------------------
extern "C" void kernel_launch(void* const* d_in, const int* in_sizes, int n_in,
                              void* d_out, int out_size) {
    const float* x     = (const float*)d_in[0];
    const float* gnw   = (const float*)d_in[1];
    const float* gnb   = (const float*)d_in[2];
    const float* qkvw  = (const float*)d_in[3];
    const float* qkvb  = (const float*)d_in[4];
    const float* projw = (const float*)d_in[5];
    const float* projb = (const float*)d_in[6];
    float* out = (float*)d_out;

    __half *xn, *wqkv, *wprj, *qkv, *P, *Oh;
    float  *S, *Of;
    cudaGetSymbolAddress((void**)&xn,   g_xn);
    cudaGetSymbolAddress((void**)&wqkv, g_wqkv);
    cudaGetSymbolAddress((void**)&wprj, g_wprj);
    cudaGetSymbolAddress((void**)&qkv,  g_qkv);
    cudaGetSymbolAddress((void**)&S,    g_S);
    cudaGetSymbolAddress((void**)&P,    g_P);
    cudaGetSymbolAddress((void**)&Oh,   g_Oh);
    cudaGetSymbolAddress((void**)&Of,   g_Of);

    const long long sXN  = (long long)CCH * NPIX;
    const long long sQKV = (long long)3 * CCH * NPIX;
    const long long sATT = (long long)NPIX * NPIX;

    // prep: weights -> fp16, groupnorm -> fp16
    repack_kernel<<<(3 * CCH * CCH + 255) / 256, 256>>>(qkvw, wqkv, 3 * CCH * CCH);
    repack_kernel<<<(CCH * CCH + 255) / 256, 256>>>(projw, wprj, CCH * CCH);
    gn_kernel<<<NBATCH * 32, 256>>>(x, gnw, gnb, xn);

    // qkv[o][n] = W[o][c] * xn[c][n] + bias[o]   (fp16 out)
    gemm_tc<1, 0, 1><<<dim3(NPIX / 128, 1536 / 128, NBATCH), 256>>>(
        wqkv, CCH, 0,
        xn, NPIX, sXN,
        qkv, NPIX, sQKV,
        CCH, qkvb, nullptr, 0, nullptr, 0);

    // S[n][m] = q[c][n] k[c][m]  (fp32 out, scale folded into softmax)
    gemm_tc<0, 0, 0><<<dim3(NPIX / 128, NPIX / 128, NBATCH), 256>>>(
        qkv, NPIX, sQKV,
        qkv + (size_t)CCH * NPIX, NPIX, sQKV,
        S, NPIX, sATT,
        CCH, nullptr, nullptr, 0, nullptr, 0);

    // P = softmax(S * scale)  (fp16)
    softmax_kernel<<<NBATCH * NPIX, 256>>>(S, P);

    // O[c][n] = V[c][m] P[n][m]  (fp16 + fp32 dual out)
    gemm_tc<1, 1, 2><<<dim3(NPIX / 128, CCH / 128, NBATCH), 256>>>(
        qkv + (size_t)2 * CCH * NPIX, NPIX, sQKV,
        P, NPIX, sATT,
        Oh, NPIX, sXN,
        NPIX, nullptr, nullptr, 0, Of, sXN);

    // out[o][n] = Wp[o][c] Oh[c][n] + projb[o] + Of[o][n]
    gemm_tc<1, 0, 3><<<dim3(NPIX / 128, CCH / 128, NBATCH), 256>>>(
        wprj, CCH, 0,
        Oh, NPIX, sXN,
        out, NPIX, sXN,
        CCH, projb, Of, sXN, nullptr, 0);
}